// round 2
// baseline (speedup 1.0000x reference)
#include <cuda_runtime.h>
#include <math_constants.h>

// Problem constants (fixed by setup_inputs): B=8, N=128, H=256, F=1023
#define B_ 8
#define N_ 128
#define H_ 256

// Scratch for per-row dot products (alloc-free rule: __device__ globals)
__device__ float g_r[B_ * N_];   // dot(x[b,i], W[0:256])
__device__ float g_s[B_ * N_];   // dot(x[b,i], W[256:512])

// ---------------------------------------------------------------------------
// Kernel 0: per-row dots with W0 and W1. One warp per row (1024 rows).
// ---------------------------------------------------------------------------
__global__ void rowdot_kernel(const float* __restrict__ x,
                              const float* __restrict__ W) {
    int warp = (blockIdx.x * blockDim.x + threadIdx.x) >> 5;
    int lane = threadIdx.x & 31;
    if (warp >= B_ * N_) return;
    const float* xr = x + warp * H_;
    float a0 = 0.f, a1 = 0.f;
#pragma unroll
    for (int k = 0; k < H_; k += 32) {
        float v = xr[k + lane];
        a0 += v * W[k + lane];
        a1 += v * W[H_ + k + lane];
    }
#pragma unroll
    for (int off = 16; off; off >>= 1) {
        a0 += __shfl_down_sync(0xffffffffu, a0, off);
        a1 += __shfl_down_sync(0xffffffffu, a1, off);
    }
    if (lane == 0) { g_r[warp] = a0; g_s[warp] = a1; }
}

// ---------------------------------------------------------------------------
// Kernel 1: main pair kernel.
// Per block: one 32x32 tile of logits[b] (grid 4x4x8 = 128 blocks, 128 thr).
// C = Xi @ (Xj * W2)^T over K=256, fused with row terms, one-hot W3 term,
// bias and mask. Mask arrives as int32 (harness converts bool -> int32).
// ---------------------------------------------------------------------------
#define BM 32
#define BN 32
#define BK 64

__global__ void __launch_bounds__(128)
pair_kernel(const float* __restrict__ x,
            const int* __restrict__ mask,
            const float* __restrict__ W,
            const float* __restrict__ bias,
            float* __restrict__ out) {
    __shared__ float As[BK][BM + 1];
    __shared__ float Bs[BK][BN + 1];

    const int t  = threadIdx.x;
    const int jt = blockIdx.x, it = blockIdx.y, bb = blockIdx.z;
    const int i0 = it * BM, j0 = jt * BN;
    const float* xb = x + bb * N_ * H_;
    const float* W2 = W + 2 * H_;

    const int lr = t >> 4;   // load row group 0..7
    const int lc = t & 15;   // float4 column 0..15 (covers 64 floats)
    const int ig = t >> 4;   // compute: 8 row-groups of 4 rows
    const int jg = t & 15;   // compute: 16 col-groups of 2 cols

    float acc[4][2] = {};

    for (int k0 = 0; k0 < H_; k0 += BK) {
#pragma unroll
        for (int rep = 0; rep < 4; rep++) {
            int row = lr + rep * 8;
            float4 av = *(const float4*)(xb + (i0 + row) * H_ + k0 + lc * 4);
            float4 bv = *(const float4*)(xb + (j0 + row) * H_ + k0 + lc * 4);
            float4 wv = *(const float4*)(W2 + k0 + lc * 4);
            As[lc * 4 + 0][row] = av.x;
            As[lc * 4 + 1][row] = av.y;
            As[lc * 4 + 2][row] = av.z;
            As[lc * 4 + 3][row] = av.w;
            Bs[lc * 4 + 0][row] = bv.x * wv.x;
            Bs[lc * 4 + 1][row] = bv.y * wv.y;
            Bs[lc * 4 + 2][row] = bv.z * wv.z;
            Bs[lc * 4 + 3][row] = bv.w * wv.w;
        }
        __syncthreads();
#pragma unroll
        for (int k = 0; k < BK; k++) {
            float a0 = As[k][ig * 4 + 0];
            float a1 = As[k][ig * 4 + 1];
            float a2 = As[k][ig * 4 + 2];
            float a3 = As[k][ig * 4 + 3];
            float b0 = Bs[k][jg * 2 + 0];
            float b1 = Bs[k][jg * 2 + 1];
            acc[0][0] += a0 * b0; acc[0][1] += a0 * b1;
            acc[1][0] += a1 * b0; acc[1][1] += a1 * b1;
            acc[2][0] += a2 * b0; acc[2][1] += a2 * b1;
            acc[3][0] += a3 * b0; acc[3][1] += a3 * b1;
        }
        __syncthreads();
    }

    const float bs = bias[0];
    const float* W3 = W + 3 * H_;
    const int* mb = mask + bb * N_;

#pragma unroll
    for (int m = 0; m < 4; m++) {
        int i = i0 + ig * 4 + m;
        // repeat_interleave quirk: one-hot row index = (b*128 + i) // 8 = b*16 + i>>3
        int aidx = bb * 16 + (i >> 3);
        float ri = g_r[bb * N_ + i] + bs;
        bool mi = mb[i] != 0;
#pragma unroll
        for (int n = 0; n < 2; n++) {
            int j = j0 + jg * 2 + n;
            float v = acc[m][n] + ri + g_s[bb * N_ + j] + W3[j + 127 - aidx];
            if (!(mi && (mb[j] != 0))) v = -CUDART_INF_F;
            out[(bb * N_ + i) * N_ + j] = v;
        }
    }
}

// ---------------------------------------------------------------------------
// Kernel 2: argmax over j per (b,i). One warp per row; first-occurrence
// tie-break matches jnp.argmax.
// ---------------------------------------------------------------------------
__global__ void argmax_kernel(const float* __restrict__ logits,
                              float* __restrict__ preds) {
    int warp = (blockIdx.x * blockDim.x + threadIdx.x) >> 5;
    int lane = threadIdx.x & 31;
    if (warp >= B_ * N_) return;
    const float* row = logits + warp * N_;
    float best = -CUDART_INF_F;
    int bi = 0;
#pragma unroll
    for (int r = 0; r < 4; r++) {
        int j = lane + r * 32;       // ascending within each thread
        float v = row[j];
        if (v > best) { best = v; bi = j; }
    }
#pragma unroll
    for (int off = 16; off; off >>= 1) {
        float ov = __shfl_down_sync(0xffffffffu, best, off);
        int   oi = __shfl_down_sync(0xffffffffu, bi, off);
        if (ov > best || (ov == best && oi < bi)) { best = ov; bi = oi; }
    }
    if (lane == 0) preds[warp] = (float)bi;
}

// ---------------------------------------------------------------------------
extern "C" void kernel_launch(void* const* d_in, const int* in_sizes, int n_in,
                              void* d_out, int out_size) {
    const float* x    = (const float*)d_in[0];   // [8,128,256] float32
    const int*   mask = (const int*)d_in[1];     // [8,128] bool -> int32
    const float* W    = (const float*)d_in[2];   // [1,1023] float32
    const float* bias = (const float*)d_in[3];   // [1] float32
    float* out = (float*)d_out;

    rowdot_kernel<<<128, 256>>>(x, W);              // 1024 warps

    dim3 grid(N_ / BN, N_ / BM, B_);                // (4,4,8)
    pair_kernel<<<grid, 128>>>(x, mask, W, bias, out);

    const int nlog = B_ * N_ * N_;                  // 131072
    if (out_size >= nlog + B_ * N_) {
        argmax_kernel<<<128, 256>>>(out, out + nlog);  // 1024 warps
    }
}